// round 1
// baseline (speedup 1.0000x reference)
#include <cuda_runtime.h>
#include <math.h>

#define T_  512
#define B_  2048
#define I_  24
#define H_  20
#define NB  4              // batch elements per block
#define TPE 40             // threads per element: 4 gate types x 10 unit-pairs
#define NTHREADS (NB*TPE)  // 160

__device__ __forceinline__ float sigf(float x) {
    // 1/(1+e^-x); e^-x may overflow to +inf for very negative x -> result 0 (correct)
    return __fdividef(1.0f, 1.0f + __expf(-x));
}

__device__ __forceinline__ float tanh_f(float x) {
    // tanh(|x|) = (1-e)/(1+e), e = exp(-2|x|) in (0,1] -> never overflows
    float a = fabsf(x);
    float e = __expf(-2.0f * a);
    float t = __fdividef(1.0f - e, 1.0f + e);
    return copysignf(t, x);
}

__global__ __launch_bounds__(NTHREADS, 3)
void providence_lstm_kernel(const float* __restrict__ x,
                            const int*   __restrict__ lens,
                            const float* __restrict__ Wih,
                            const float* __restrict__ Whh,
                            const float* __restrict__ bih,
                            const float* __restrict__ bhh,
                            const float* __restrict__ Wa,
                            const float* __restrict__ ba,
                            const float* __restrict__ Wb,
                            const float* __restrict__ bb,
                            float* __restrict__ out)
{
    __shared__ float xbuf[2][NB][I_];     // double-buffered x[t] slice
    __shared__ float hbuf[NB][H_];        // current hidden state
    __shared__ float gbuf[NB][4][H_];     // gates i,f,g,o for this step
    __shared__ float Was[H_], Wbs[H_];
    __shared__ float ba_s, bb_s;

    const int tid = threadIdx.x;
    const int e   = tid / TPE;        // element within block (0..3)
    const int r   = tid % TPE;        // role within element (0..39)
    const int g   = r / 10;           // gate type 0:i 1:f 2:g 3:o
    const int jj  = r % 10;           // unit-pair index
    const int bg  = blockIdx.x * NB + e;   // global batch index

    const int row0 = g * H_ + jj;     // rows in [4H, *] weight matrices
    const int row1 = row0 + 10;

    // Per-thread weights in registers: 2 gate rows of W_ih and W_hh
    float wih0[I_], wih1[I_], whh0[H_], whh1[H_];
    #pragma unroll
    for (int i = 0; i < I_; i++) { wih0[i] = Wih[row0*I_ + i]; wih1[i] = Wih[row1*I_ + i]; }
    #pragma unroll
    for (int k = 0; k < H_; k++) { whh0[k] = Whh[row0*H_ + k]; whh1[k] = Whh[row1*H_ + k]; }
    const float bias0 = bih[row0] + bhh[row0];
    const float bias1 = bih[row1] + bhh[row1];

    if (tid < H_) { Was[tid] = Wa[tid]; Wbs[tid] = Wb[tid]; }
    if (tid == 0) { ba_s = ba[0]; bb_s = bb[0]; }
    if (r < H_)   hbuf[e][r] = 0.0f;
    float c = 0.0f;                    // cell state, valid for r < H_

    const int mylen = lens[bg];

    // preload x[0]
    if (r < I_) xbuf[0][e][r] = x[(size_t)bg * I_ + r];
    __syncthreads();

    for (int t = 0; t < T_; t++) {
        const int cur = t & 1;

        // ---- Phase A: compute 2 gate pre-activations (88 FMAs, 44 LDS) ----
        float a0 = bias0, a1 = bias1;
        #pragma unroll
        for (int i = 0; i < I_; i++) {
            float xv = xbuf[cur][e][i];
            a0 = fmaf(wih0[i], xv, a0);
            a1 = fmaf(wih1[i], xv, a1);
        }
        #pragma unroll
        for (int k = 0; k < H_; k++) {
            float hv = hbuf[e][k];
            a0 = fmaf(whh0[k], hv, a0);
            a1 = fmaf(whh1[k], hv, a1);
        }
        gbuf[e][g][jj]      = a0;
        gbuf[e][g][jj + 10] = a1;

        // prefetch next timestep's x into the other buffer
        if (t + 1 < T_ && r < I_)
            xbuf[cur ^ 1][e][r] = x[(size_t)(t + 1) * (B_ * I_) + (size_t)bg * I_ + r];

        __syncthreads();

        // ---- Phase B: state update (threads r<H_ own one unit each) ----
        if (r < H_) {
            const int u = r;
            float gi = gbuf[e][0][u];
            float gf = gbuf[e][1][u];
            float gg = gbuf[e][2][u];
            float go = gbuf[e][3][u];
            float si = sigf(gi), sf = sigf(gf), so = sigf(go);
            c = sf * c + si * tanh_f(gg);
            hbuf[e][u] = so * tanh_f(c);
        }
        __syncthreads();

        // ---- Phase C: output heads (masked). h reads race-free until next
        //      phase-B write, which is behind the next barrier. ----
        if (r == 20) {
            float z = ba_s;
            #pragma unroll
            for (int k = 0; k < H_; k++) z = fmaf(hbuf[e][k], Was[k], z);
            if (t >= mylen) z = ba_s;              // h == 0 in masked region
            out[(size_t)t * B_ + bg] = __expf(z);  // alpha
        } else if (r == 21) {
            float z = bb_s;
            #pragma unroll
            for (int k = 0; k < H_; k++) z = fmaf(hbuf[e][k], Wbs[k], z);
            if (t >= mylen) z = bb_s;
            // softplus, overflow-safe
            float sp = fmaxf(z, 0.0f) + log1pf(__expf(-fabsf(z)));
            out[(size_t)(T_ * B_) + (size_t)t * B_ + bg] = sp;  // beta
        }
    }
}

extern "C" void kernel_launch(void* const* d_in, const int* in_sizes, int n_in,
                              void* d_out, int out_size)
{
    // Identify inputs by element count (robust to index shuffles); the two
    // 80-sized biases are summed so their order is irrelevant; 20- and
    // 1-sized pairs keep dict order (W_a,b_a before W_b,b_b).
    const float *x = 0, *Wih = 0, *Whh = 0, *bih = 0, *bhh = 0;
    const float *Wa = 0, *ba = 0, *Wb = 0, *bb = 0;
    const int *lens = 0;
    int seen80 = 0, seen20 = 0, seen1 = 0;
    for (int i = 0; i < n_in; i++) {
        int s = in_sizes[i];
        if      (s == T_ * B_ * I_) x    = (const float*)d_in[i];
        else if (s == B_)           lens = (const int*)d_in[i];
        else if (s == 4*H_ * I_)    Wih  = (const float*)d_in[i];
        else if (s == 4*H_ * H_)    Whh  = (const float*)d_in[i];
        else if (s == 4*H_) { if (seen80++ == 0) bih = (const float*)d_in[i]; else bhh = (const float*)d_in[i]; }
        else if (s == H_)   { if (seen20++ == 0) Wa  = (const float*)d_in[i]; else Wb  = (const float*)d_in[i]; }
        else if (s == 1)    { if (seen1++  == 0) ba  = (const float*)d_in[i]; else bb  = (const float*)d_in[i]; }
    }

    float* out = (float*)d_out;
    dim3 grid(B_ / NB);      // 512 blocks
    dim3 block(NTHREADS);    // 160 threads
    providence_lstm_kernel<<<grid, block>>>(x, lens, Wih, Whh, bih, bhh,
                                            Wa, ba, Wb, bb, out);
}